// round 10
// baseline (speedup 1.0000x reference)
#include <cuda_runtime.h>
#include <cuda_fp16.h>
#include <cstdint>
#include <cstddef>

#define G   256
#define CH  128
#define HD  64
#define NTHREADS 256

// ---- smem byte offsets (tiles: [row][64 halves] = 128B rows, SW128 swizzle) ----
#define SB_OFF  0                        // bias: 192 floats
#define XT_OFF  1024                     // 2 x [256][64] fp16 (ch-chunks) = 64 KB
#define WT_OFF  (XT_OFF + 2*32768)       // 2 x [192][64] fp16 (ch-chunks) = 48 KB
#define K_OFF   (WT_OFF + 2*24576)       // [256][64] fp16                 = 32 KB
#define V_OFF   (K_OFF  + 32768)         // [256][64] fp16                 = 32 KB
#define SMEM_BYTES (V_OFF + 32768)       // 181248

#define SWZ(o) ((o) ^ (((o) >> 3) & 0x70))
#define ESC2 0.12751744f                 // (1/sqrt(128)) * log2(e)

__device__ __forceinline__ uint32_t smem_u32(const void* p) {
    uint32_t a;
    asm("{ .reg .u64 t; cvta.to.shared.u64 t, %1; cvt.u32.u64 %0, t; }" : "=r"(a) : "l"(p));
    return a;
}
__device__ __forceinline__ uint32_t h2u(float a, float b) {
    __half2 h = __floats2half2_rn(a, b);
    return *reinterpret_cast<uint32_t*>(&h);
}
__device__ __forceinline__ float ex2f(float x) {
    float r; asm("ex2.approx.f32 %0, %1;" : "=f"(r) : "f"(x)); return r;
}
__device__ __forceinline__ void ldsm4(uint32_t* r, uint32_t addr) {
    asm volatile("ldmatrix.sync.aligned.m8n8.x4.shared.b16 {%0,%1,%2,%3}, [%4];"
                 : "=r"(r[0]), "=r"(r[1]), "=r"(r[2]), "=r"(r[3]) : "r"(addr));
}
__device__ __forceinline__ void ldsm4t(uint32_t* r, uint32_t addr) {
    asm volatile("ldmatrix.sync.aligned.m8n8.x4.trans.shared.b16 {%0,%1,%2,%3}, [%4];"
                 : "=r"(r[0]), "=r"(r[1]), "=r"(r[2]), "=r"(r[3]) : "r"(addr));
}
__device__ __forceinline__ void mma16816(float* d, const uint32_t* a, uint32_t b0, uint32_t b1) {
    asm volatile("mma.sync.aligned.m16n8k16.row.col.f32.f16.f16.f32 "
        "{%0,%1,%2,%3}, {%4,%5,%6,%7}, {%8,%9}, {%0,%1,%2,%3};"
        : "+f"(d[0]), "+f"(d[1]), "+f"(d[2]), "+f"(d[3])
        : "r"(a[0]), "r"(a[1]), "r"(a[2]), "r"(a[3]), "r"(b0), "r"(b1));
}

__global__ void __launch_bounds__(NTHREADS, 1)
msa_hmma8(const float* __restrict__ x, const float* __restrict__ W,
          const float* __restrict__ bias, float* __restrict__ out,
          int nGroups, int step)
{
    extern __shared__ char smem[];
    const uint32_t sb = smem_u32(smem);
    float* sB = reinterpret_cast<float*>(smem + SB_OFF);

    const int h  = blockIdx.x & 1;     // step is even -> h constant per CTA
    const int t  = threadIdx.x;
    const int w  = t >> 5, lane = t & 31;
    const int q2 = 2 * (lane & 3);

    // lane-dependent fragment pieces (inside one 2048B swizzle span)
    const int nl  = (lane & 7) + ((lane & 16) ? 8 : 0);   // B-frag row (K/W)
    const int cb8 = (lane & 8) ? 16 : 0;                   // B-frag col byte bit
    const int tl  = (lane & 7) + ((lane & 8) ? 8 : 0);     // V trans row piece
    const int vb8 = (lane & 16) ? 16 : 0;                  // V trans col byte bit

    uint32_t waddr[4], kaddr[4], vaddr[4];
    #pragma unroll
    for (int ks = 0; ks < 4; ks++) {
        waddr[ks] = sb + WT_OFF + SWZ((uint32_t)(nl * 128 + ks * 32 + cb8));
        kaddr[ks] = sb + K_OFF  + SWZ((uint32_t)(nl * 128 + ks * 32 + cb8));
    }
    #pragma unroll
    for (int j = 0; j < 4; j++)
        vaddr[j] = sb + V_OFF + SWZ((uint32_t)(tl * 128 + 32 * j + vb8));

    // X staging per-thread constants: linear f4-index g = k*256+t
    //   c4 = t&31 (const), row = 8k + w  ->  dst = base + k*1024 (swizzle-safe)
    const int c4   = t & 31;
    const int xdst = XT_OFF + (c4 >> 4) * 32768 +
                     (int)SWZ((uint32_t)(w * 128 + (c4 & 15) * 8));

    // ---- one-time: W slice (h fixed) + bias ----
    #pragma unroll 4
    for (int k = 0; k < 24; k++) {
        const int row = 8 * k + w;
        const int grow = (row >> 6) * CH + h * HD + (row & 63);
        float4 v = reinterpret_cast<const float4*>(W + (size_t)grow * CH)[c4];
        *reinterpret_cast<uint2*>(smem + WT_OFF + (c4 >> 4) * 24576 +
                                  SWZ(row * 128 + (c4 & 15) * 8)) =
            make_uint2(h2u(v.x, v.y), h2u(v.z, v.w));
    }
    if (t < 192) sB[t] = bias[(t >> 6) * CH + h * HD + (t & 63)];

    // ---- stage X for this CTA's first group ----
    {
        const float4* xg = reinterpret_cast<const float4*>(
            x + (size_t)(blockIdx.x >> 1) * (G * CH)) + t;
        #pragma unroll 8
        for (int k = 0; k < 32; k++) {
            float4 v = xg[k * 256];
            *reinterpret_cast<uint2*>(smem + xdst + k * 1024) =
                make_uint2(h2u(v.x, v.y), h2u(v.z, v.w));
        }
    }

    const int row0 = 32 * w + (lane >> 2);

    for (int g = blockIdx.x; g < nGroups; g += step) {
        const int bl = g >> 1;
        const bool hasNext = (g + step) < nGroups;
        const float4* xn = reinterpret_cast<const float4*>(
            x + (size_t)((hasNext ? (g + step) : g) >> 1) * (G * CH)) + t;

        __syncthreads();   // XT staged (prev iter / prologue); K/V free to overwrite

        // ============ phase 1: QKV GEMM, warp = 32 rows x 192 cols ============
        uint32_t xa[2][8][4];
        #pragma unroll
        for (int m = 0; m < 2; m++)
            #pragma unroll
            for (int ks = 0; ks < 8; ks++) {
                const int r = 32 * w + 16 * m + (lane & 15);
                ldsm4(xa[m][ks], sb + XT_OFF + (ks >> 2) * 32768 +
                      SWZ((uint32_t)(r * 128 + (ks & 3) * 32 + ((lane & 16) ? 16 : 0))));
            }

        uint32_t qa[2][4][4];                // Q as phase-2 A-fragments (in regs)

        #pragma unroll
        for (int chk = 0; chk < 6; chk++) {  // 6 x 32 output cols: QQ KK VV
            float fa[2][4][4];
            #pragma unroll
            for (int m = 0; m < 2; m++)
                #pragma unroll
                for (int jb = 0; jb < 4; jb++) {
                    fa[m][jb][0]=0.f; fa[m][jb][1]=0.f; fa[m][jb][2]=0.f; fa[m][jb][3]=0.f;
                }

            #pragma unroll
            for (int ks = 0; ks < 8; ks++)
                #pragma unroll
                for (int j = 0; j < 2; j++) {
                    uint32_t b[4];
                    ldsm4(b, waddr[ks & 3] + (uint32_t)((ks >> 2) * 24576 + chk * 4096 + j * 2048));
                    mma16816(fa[0][2*j],   xa[0][ks], b[0], b[1]);
                    mma16816(fa[0][2*j+1], xa[0][ks], b[2], b[3]);
                    mma16816(fa[1][2*j],   xa[1][ks], b[0], b[1]);
                    mma16816(fa[1][2*j+1], xa[1][ks], b[2], b[3]);
                }

            if (chk < 2) {
                #pragma unroll
                for (int m = 0; m < 2; m++)
                    #pragma unroll
                    for (int kl = 0; kl < 2; kl++) {
                        const float b0 = sB[chk*32 + 16*kl + q2],     b1 = sB[chk*32 + 16*kl + q2 + 1];
                        const float b2 = sB[chk*32 + 16*kl + q2 + 8], b3 = sB[chk*32 + 16*kl + q2 + 9];
                        qa[m][2*chk+kl][0] = h2u((fa[m][2*kl][0]  + b0) * ESC2, (fa[m][2*kl][1]  + b1) * ESC2);
                        qa[m][2*chk+kl][1] = h2u((fa[m][2*kl][2]  + b0) * ESC2, (fa[m][2*kl][3]  + b1) * ESC2);
                        qa[m][2*chk+kl][2] = h2u((fa[m][2*kl+1][0]+ b2) * ESC2, (fa[m][2*kl+1][1]+ b3) * ESC2);
                        qa[m][2*chk+kl][3] = h2u((fa[m][2*kl+1][2]+ b2) * ESC2, (fa[m][2*kl+1][3]+ b3) * ESC2);
                    }
            } else {
                char* dst = smem + (chk < 4 ? K_OFF : V_OFF);
                const int col0 = (chk & 1) * 32;
                #pragma unroll
                for (int m = 0; m < 2; m++) {
                    const int r0 = row0 + 16 * m;
                    #pragma unroll
                    for (int jb = 0; jb < 4; jb++) {
                        const int cc = col0 + 8 * jb + q2;
                        const float b0 = sB[chk*32 + 8*jb + q2], b1 = sB[chk*32 + 8*jb + q2 + 1];
                        *reinterpret_cast<uint32_t*>(dst + SWZ( r0      * 128 + cc * 2)) =
                            h2u(fa[m][jb][0] + b0, fa[m][jb][1] + b1);
                        *reinterpret_cast<uint32_t*>(dst + SWZ((r0 + 8) * 128 + cc * 2)) =
                            h2u(fa[m][jb][2] + b0, fa[m][jb][3] + b1);
                    }
                }
            }
        }
        __syncthreads();   // K/V ready; XT now dead -> staging target

        // ============ phase 2: attention + pipelined staging of next X ============
        float oacc[2][8][4];
        #pragma unroll
        for (int m = 0; m < 2; m++)
            #pragma unroll
            for (int jb = 0; jb < 8; jb++) {
                oacc[m][jb][0]=0.f; oacc[m][jb][1]=0.f; oacc[m][jb][2]=0.f; oacc[m][jb][3]=0.f;
            }
        float rsum[2][2] = {{0.f,0.f},{0.f,0.f}};

        #pragma unroll
        for (int kv = 0; kv < 4; kv++) {
            float sacc[2][8][4];
            #pragma unroll
            for (int m = 0; m < 2; m++)
                #pragma unroll
                for (int jb = 0; jb < 8; jb++) {
                    sacc[m][jb][0]=0.f; sacc[m][jb][1]=0.f; sacc[m][jb][2]=0.f; sacc[m][jb][3]=0.f;
                }

            #pragma unroll
            for (int ks = 0; ks < 4; ks++)
                #pragma unroll
                for (int j = 0; j < 4; j++) {
                    uint32_t b[4];
                    ldsm4(b, kaddr[ks] + (uint32_t)(kv * 8192 + j * 2048));
                    mma16816(sacc[0][2*j],   qa[0][ks], b[0], b[1]);
                    mma16816(sacc[0][2*j+1], qa[0][ks], b[2], b[3]);
                    mma16816(sacc[1][2*j],   qa[1][ks], b[0], b[1]);
                    mma16816(sacc[1][2*j+1], qa[1][ks], b[2], b[3]);
                }

            uint32_t pf[2][4][4];
            #pragma unroll
            for (int m = 0; m < 2; m++)
                #pragma unroll
                for (int ks = 0; ks < 4; ks++) {
                    float e0 = ex2f(sacc[m][2*ks][0]),   e1 = ex2f(sacc[m][2*ks][1]);
                    float e2 = ex2f(sacc[m][2*ks][2]),   e3 = ex2f(sacc[m][2*ks][3]);
                    float f0 = ex2f(sacc[m][2*ks+1][0]), f1 = ex2f(sacc[m][2*ks+1][1]);
                    float f2 = ex2f(sacc[m][2*ks+1][2]), f3 = ex2f(sacc[m][2*ks+1][3]);
                    rsum[m][0] += (e0 + e1) + (f0 + f1);
                    rsum[m][1] += (e2 + e3) + (f2 + f3);
                    pf[m][ks][0] = h2u(e0, e1);
                    pf[m][ks][1] = h2u(e2, e3);
                    pf[m][ks][2] = h2u(f0, f1);
                    pf[m][ks][3] = h2u(f2, f3);
                }

            #pragma unroll
            for (int ks = 0; ks < 4; ks++)
                #pragma unroll
                for (int j = 0; j < 4; j++) {
                    uint32_t b[4];
                    ldsm4t(b, vaddr[j] + (uint32_t)(kv * 8192 + ks * 2048));
                    mma16816(oacc[0][2*j],   pf[0][ks], b[0], b[1]);
                    mma16816(oacc[0][2*j+1], pf[0][ks], b[2], b[3]);
                    mma16816(oacc[1][2*j],   pf[1][ks], b[0], b[1]);
                    mma16816(oacc[1][2*j+1], pf[1][ks], b[2], b[3]);
                }

            // ---- stage next group's X slice (XT dead during phase 2) ----
            if (hasNext) {
                #pragma unroll
                for (int i = 0; i < 8; i++) {
                    const int k = kv * 8 + i;
                    float4 v = xn[k * 256];
                    *reinterpret_cast<uint2*>(smem + xdst + k * 1024) =
                        make_uint2(h2u(v.x, v.y), h2u(v.z, v.w));
                }
            }
        }

        // normalize + write out (both msubs)
        #pragma unroll
        for (int m = 0; m < 2; m++) {
            float r0s = rsum[m][0], r1s = rsum[m][1];
            r0s += __shfl_xor_sync(0xffffffffu, r0s, 1);
            r0s += __shfl_xor_sync(0xffffffffu, r0s, 2);
            r1s += __shfl_xor_sync(0xffffffffu, r1s, 1);
            r1s += __shfl_xor_sync(0xffffffffu, r1s, 2);
            const float inv0 = 1.0f / r0s, inv1 = 1.0f / r1s;

            float* o = out + ((size_t)(bl * G) + row0 + 16 * m) * CH + h * HD;
            #pragma unroll
            for (int jb = 0; jb < 8; jb++) {
                const int c = 8 * jb + q2;
                *reinterpret_cast<float2*>(o + c) =
                    make_float2(oacc[m][jb][0] * inv0, oacc[m][jb][1] * inv0);
                *reinterpret_cast<float2*>(o + 8 * CH + c) =
                    make_float2(oacc[m][jb][2] * inv1, oacc[m][jb][3] * inv1);
            }
        }
    }
}

extern "C" void kernel_launch(void* const* d_in, const int* in_sizes, int n_in,
                              void* d_out, int out_size) {
    (void)n_in; (void)out_size;
    const float* x  = (const float*)d_in[0];
    const float* W  = (const float*)d_in[1];
    const float* b  = (const float*)d_in[2];
    float* out = (float*)d_out;

    cudaFuncSetAttribute(msa_hmma8, cudaFuncAttributeMaxDynamicSharedMemorySize, SMEM_BYTES);

    int nbl = in_sizes[0] / (G * CH);   // 512 (b,l) groups
    int nGroups = nbl * 2;

    int dev = 0, sms = 148;
    cudaGetDevice(&dev);
    cudaDeviceGetAttribute(&sms, cudaDevAttrMultiProcessorCount, dev);
    sms &= ~1;                          // even stride -> per-CTA head parity fixed
    if (sms < 2) sms = 2;
    if (sms > nGroups) sms = nGroups;

    msa_hmma8<<<sms, NTHREADS, SMEM_BYTES>>>(x, W, b, out, nGroups, sms);
}

// round 11
// speedup vs baseline: 1.1758x; 1.1758x over previous
#include <cuda_runtime.h>
#include <cuda_fp16.h>
#include <cstdint>
#include <cstddef>

#define G   256
#define CH  128
#define HD  64
#define NTHREADS 256

// ---- smem byte offsets (tiles: [row][64 halves] = 128B rows, SW128 swizzle) ----
#define SB_OFF  0                        // bias: 192 floats
#define XT_OFF  1024                     // 2 x [256][64] fp16 (ch-chunks) = 64 KB
#define WT_OFF  (XT_OFF + 2*32768)       // 2 x [192][64] fp16 (ch-chunks) = 48 KB
#define K_OFF   (WT_OFF + 2*24576)       // [256][64] fp16                 = 32 KB
#define V_OFF   (K_OFF  + 32768)         // [256][64] fp16                 = 32 KB
#define SMEM_BYTES (V_OFF + 32768)       // 181248

#define SWZ(o) ((o) ^ (((o) >> 3) & 0x70))
#define ESC2 0.12751744f                 // (1/sqrt(128)) * log2(e)

__device__ __forceinline__ uint32_t smem_u32(const void* p) {
    uint32_t a;
    asm("{ .reg .u64 t; cvta.to.shared.u64 t, %1; cvt.u32.u64 %0, t; }" : "=r"(a) : "l"(p));
    return a;
}
__device__ __forceinline__ uint32_t h2u(float a, float b) {
    __half2 h = __floats2half2_rn(a, b);
    return *reinterpret_cast<uint32_t*>(&h);
}
__device__ __forceinline__ float ex2f(float x) {
    float r; asm("ex2.approx.f32 %0, %1;" : "=f"(r) : "f"(x)); return r;
}
__device__ __forceinline__ void ldsm4(uint32_t* r, uint32_t addr) {
    asm volatile("ldmatrix.sync.aligned.m8n8.x4.shared.b16 {%0,%1,%2,%3}, [%4];"
                 : "=r"(r[0]), "=r"(r[1]), "=r"(r[2]), "=r"(r[3]) : "r"(addr));
}
__device__ __forceinline__ void ldsm4t(uint32_t* r, uint32_t addr) {
    asm volatile("ldmatrix.sync.aligned.m8n8.x4.trans.shared.b16 {%0,%1,%2,%3}, [%4];"
                 : "=r"(r[0]), "=r"(r[1]), "=r"(r[2]), "=r"(r[3]) : "r"(addr));
}
__device__ __forceinline__ void mma16816(float* d, const uint32_t* a, uint32_t b0, uint32_t b1) {
    asm volatile("mma.sync.aligned.m16n8k16.row.col.f32.f16.f16.f32 "
        "{%0,%1,%2,%3}, {%4,%5,%6,%7}, {%8,%9}, {%0,%1,%2,%3};"
        : "+f"(d[0]), "+f"(d[1]), "+f"(d[2]), "+f"(d[3])
        : "r"(a[0]), "r"(a[1]), "r"(a[2]), "r"(a[3]), "r"(b0), "r"(b1));
}

__global__ void __launch_bounds__(NTHREADS, 1)
msa_hmma9(const float* __restrict__ x, const float* __restrict__ W,
          const float* __restrict__ bias, float* __restrict__ out,
          int nGroups, int step)
{
    extern __shared__ char smem[];
    const uint32_t sb = smem_u32(smem);
    float* sB = reinterpret_cast<float*>(smem + SB_OFF);

    const int h  = blockIdx.x & 1;     // step is even -> h constant per CTA
    const int t  = threadIdx.x;
    const int w  = t >> 5, lane = t & 31;
    const int q2 = 2 * (lane & 3);

    const int nl  = (lane & 7) + ((lane & 16) ? 8 : 0);   // B-frag row (K/W)
    const int cb8 = (lane & 8) ? 16 : 0;
    const int tl  = (lane & 7) + ((lane & 8) ? 8 : 0);    // V trans row piece
    const int vb8 = (lane & 16) ? 16 : 0;

    uint32_t waddr[4], kaddr[4], vaddr[4];
    #pragma unroll
    for (int ks = 0; ks < 4; ks++) {
        waddr[ks] = sb + WT_OFF + SWZ((uint32_t)(nl * 128 + ks * 32 + cb8));
        kaddr[ks] = sb + K_OFF  + SWZ((uint32_t)(nl * 128 + ks * 32 + cb8));
    }
    #pragma unroll
    for (int j = 0; j < 4; j++)
        vaddr[j] = sb + V_OFF + SWZ((uint32_t)(tl * 128 + 32 * j + vb8));

    // X staging per-thread constants: linear f4-index g = k*256+t
    const int c4   = t & 31;
    const int xdst = XT_OFF + (c4 >> 4) * 32768 +
                     (int)SWZ((uint32_t)(w * 128 + (c4 & 15) * 8));

    // ---- one-time: W slice (h fixed) + bias ----
    #pragma unroll 4
    for (int k = 0; k < 24; k++) {
        const int row = 8 * k + w;
        const int grow = (row >> 6) * CH + h * HD + (row & 63);
        float4 v = reinterpret_cast<const float4*>(W + (size_t)grow * CH)[c4];
        *reinterpret_cast<uint2*>(smem + WT_OFF + (c4 >> 4) * 24576 +
                                  SWZ(row * 128 + (c4 & 15) * 8)) =
            make_uint2(h2u(v.x, v.y), h2u(v.z, v.w));
    }
    if (t < 192) sB[t] = bias[(t >> 6) * CH + h * HD + (t & 63)];

    // ---- stage X for this CTA's first group (bulk, MLP=32) ----
    {
        const float4* xg = reinterpret_cast<const float4*>(
            x + (size_t)(blockIdx.x >> 1) * (G * CH)) + t;
        #pragma unroll 8
        for (int k = 0; k < 32; k++) {
            float4 v = xg[k * 256];
            *reinterpret_cast<uint2*>(smem + xdst + k * 1024) =
                make_uint2(h2u(v.x, v.y), h2u(v.z, v.w));
        }
    }

    const int row0 = 32 * w + (lane >> 2);

    for (int g = blockIdx.x; g < nGroups; g += step) {
        const int bl = g >> 1;
        const bool hasNext = (g + step) < nGroups;
        const float4* xn = reinterpret_cast<const float4*>(
            x + (size_t)((hasNext ? (g + step) : g) >> 1) * (G * CH)) + t;

        __syncthreads();   // XT staged (prev iter / prologue); K/V free to overwrite

        // ============ phase 1: QKV GEMM, warp = 32 rows x 192 cols ============
        uint32_t xa[2][8][4];
        #pragma unroll
        for (int m = 0; m < 2; m++)
            #pragma unroll
            for (int ks = 0; ks < 8; ks++) {
                const int r = 32 * w + 16 * m + (lane & 15);
                ldsm4(xa[m][ks], sb + XT_OFF + (ks >> 2) * 32768 +
                      SWZ((uint32_t)(r * 128 + (ks & 3) * 32 + ((lane & 16) ? 16 : 0))));
            }

        uint32_t qa[2][4][4];                // Q as phase-2 A-fragments (in regs)

        #pragma unroll
        for (int chk = 0; chk < 6; chk++) {  // 6 x 32 output cols: QQ KK VV
            float fa[2][4][4];
            #pragma unroll
            for (int m = 0; m < 2; m++)
                #pragma unroll
                for (int jb = 0; jb < 4; jb++) {
                    fa[m][jb][0]=0.f; fa[m][jb][1]=0.f; fa[m][jb][2]=0.f; fa[m][jb][3]=0.f;
                }

            #pragma unroll
            for (int ks = 0; ks < 8; ks++)
                #pragma unroll
                for (int j = 0; j < 2; j++) {
                    uint32_t b[4];
                    ldsm4(b, waddr[ks & 3] + (uint32_t)((ks >> 2) * 24576 + chk * 4096 + j * 2048));
                    mma16816(fa[0][2*j],   xa[0][ks], b[0], b[1]);
                    mma16816(fa[0][2*j+1], xa[0][ks], b[2], b[3]);
                    mma16816(fa[1][2*j],   xa[1][ks], b[0], b[1]);
                    mma16816(fa[1][2*j+1], xa[1][ks], b[2], b[3]);
                }

            if (chk < 2) {
                #pragma unroll
                for (int m = 0; m < 2; m++)
                    #pragma unroll
                    for (int kl = 0; kl < 2; kl++) {
                        const float b0 = sB[chk*32 + 16*kl + q2],     b1 = sB[chk*32 + 16*kl + q2 + 1];
                        const float b2 = sB[chk*32 + 16*kl + q2 + 8], b3 = sB[chk*32 + 16*kl + q2 + 9];
                        qa[m][2*chk+kl][0] = h2u((fa[m][2*kl][0]  + b0) * ESC2, (fa[m][2*kl][1]  + b1) * ESC2);
                        qa[m][2*chk+kl][1] = h2u((fa[m][2*kl][2]  + b0) * ESC2, (fa[m][2*kl][3]  + b1) * ESC2);
                        qa[m][2*chk+kl][2] = h2u((fa[m][2*kl+1][0]+ b2) * ESC2, (fa[m][2*kl+1][1]+ b3) * ESC2);
                        qa[m][2*chk+kl][3] = h2u((fa[m][2*kl+1][2]+ b2) * ESC2, (fa[m][2*kl+1][3]+ b3) * ESC2);
                    }
            } else {
                char* dst = smem + (chk < 4 ? K_OFF : V_OFF);
                const int col0 = (chk & 1) * 32;
                #pragma unroll
                for (int m = 0; m < 2; m++) {
                    const int r0 = row0 + 16 * m;
                    #pragma unroll
                    for (int jb = 0; jb < 4; jb++) {
                        const int cc = col0 + 8 * jb + q2;
                        const float b0 = sB[chk*32 + 8*jb + q2], b1 = sB[chk*32 + 8*jb + q2 + 1];
                        *reinterpret_cast<uint32_t*>(dst + SWZ( r0      * 128 + cc * 2)) =
                            h2u(fa[m][jb][0] + b0, fa[m][jb][1] + b1);
                        *reinterpret_cast<uint32_t*>(dst + SWZ((r0 + 8) * 128 + cc * 2)) =
                            h2u(fa[m][jb][2] + b0, fa[m][jb][3] + b1);
                    }
                }
            }
        }
        __syncthreads();   // K/V ready; XT now dead -> staging target

        // ============ phase 2: attention + latency-hidden staging of next X ========
        float oacc[2][8][4];
        #pragma unroll
        for (int m = 0; m < 2; m++)
            #pragma unroll
            for (int jb = 0; jb < 8; jb++) {
                oacc[m][jb][0]=0.f; oacc[m][jb][1]=0.f; oacc[m][jb][2]=0.f; oacc[m][jb][3]=0.f;
            }
        float rsum[2][2] = {{0.f,0.f},{0.f,0.f}};

        #pragma unroll
        for (int kv = 0; kv < 4; kv++) {
            // ---- issue next-X loads EARLY: consumed after PV (latency hidden) ----
            float4 xv[8];
            if (hasNext) {
                #pragma unroll
                for (int i = 0; i < 8; i++)
                    xv[i] = xn[(kv * 8 + i) * 256];
            }

            float sacc[2][8][4];
            #pragma unroll
            for (int m = 0; m < 2; m++)
                #pragma unroll
                for (int jb = 0; jb < 8; jb++) {
                    sacc[m][jb][0]=0.f; sacc[m][jb][1]=0.f; sacc[m][jb][2]=0.f; sacc[m][jb][3]=0.f;
                }

            #pragma unroll
            for (int ks = 0; ks < 4; ks++)
                #pragma unroll
                for (int j = 0; j < 4; j++) {
                    uint32_t b[4];
                    ldsm4(b, kaddr[ks] + (uint32_t)(kv * 8192 + j * 2048));
                    mma16816(sacc[0][2*j],   qa[0][ks], b[0], b[1]);
                    mma16816(sacc[0][2*j+1], qa[0][ks], b[2], b[3]);
                    mma16816(sacc[1][2*j],   qa[1][ks], b[0], b[1]);
                    mma16816(sacc[1][2*j+1], qa[1][ks], b[2], b[3]);
                }

            uint32_t pf[2][4][4];
            #pragma unroll
            for (int m = 0; m < 2; m++)
                #pragma unroll
                for (int ks = 0; ks < 4; ks++) {
                    float e0 = ex2f(sacc[m][2*ks][0]),   e1 = ex2f(sacc[m][2*ks][1]);
                    float e2 = ex2f(sacc[m][2*ks][2]),   e3 = ex2f(sacc[m][2*ks][3]);
                    float f0 = ex2f(sacc[m][2*ks+1][0]), f1 = ex2f(sacc[m][2*ks+1][1]);
                    float f2 = ex2f(sacc[m][2*ks+1][2]), f3 = ex2f(sacc[m][2*ks+1][3]);
                    rsum[m][0] += (e0 + e1) + (f0 + f1);
                    rsum[m][1] += (e2 + e3) + (f2 + f3);
                    pf[m][ks][0] = h2u(e0, e1);
                    pf[m][ks][1] = h2u(e2, e3);
                    pf[m][ks][2] = h2u(f0, f1);
                    pf[m][ks][3] = h2u(f2, f3);
                }

            #pragma unroll
            for (int ks = 0; ks < 4; ks++)
                #pragma unroll
                for (int j = 0; j < 4; j++) {
                    uint32_t b[4];
                    ldsm4t(b, vaddr[j] + (uint32_t)(kv * 8192 + ks * 2048));
                    mma16816(oacc[0][2*j],   pf[0][ks], b[0], b[1]);
                    mma16816(oacc[0][2*j+1], pf[0][ks], b[2], b[3]);
                    mma16816(oacc[1][2*j],   pf[1][ks], b[0], b[1]);
                    mma16816(oacc[1][2*j+1], pf[1][ks], b[2], b[3]);
                }

            // ---- convert + store the staged slice (loads long since landed) ----
            if (hasNext) {
                #pragma unroll
                for (int i = 0; i < 8; i++) {
                    *reinterpret_cast<uint2*>(smem + xdst + (kv * 8 + i) * 1024) =
                        make_uint2(h2u(xv[i].x, xv[i].y), h2u(xv[i].z, xv[i].w));
                }
            }
        }

        // normalize + write out (both msubs)
        #pragma unroll
        for (int m = 0; m < 2; m++) {
            float r0s = rsum[m][0], r1s = rsum[m][1];
            r0s += __shfl_xor_sync(0xffffffffu, r0s, 1);
            r0s += __shfl_xor_sync(0xffffffffu, r0s, 2);
            r1s += __shfl_xor_sync(0xffffffffu, r1s, 1);
            r1s += __shfl_xor_sync(0xffffffffu, r1s, 2);
            const float inv0 = 1.0f / r0s, inv1 = 1.0f / r1s;

            float* o = out + ((size_t)(bl * G) + row0 + 16 * m) * CH + h * HD;
            #pragma unroll
            for (int jb = 0; jb < 8; jb++) {
                const int c = 8 * jb + q2;
                *reinterpret_cast<float2*>(o + c) =
                    make_float2(oacc[m][jb][0] * inv0, oacc[m][jb][1] * inv0);
                *reinterpret_cast<float2*>(o + 8 * CH + c) =
                    make_float2(oacc[m][jb][2] * inv1, oacc[m][jb][3] * inv1);
            }
        }
    }
}

extern "C" void kernel_launch(void* const* d_in, const int* in_sizes, int n_in,
                              void* d_out, int out_size) {
    (void)n_in; (void)out_size;
    const float* x  = (const float*)d_in[0];
    const float* W  = (const float*)d_in[1];
    const float* b  = (const float*)d_in[2];
    float* out = (float*)d_out;

    cudaFuncSetAttribute(msa_hmma9, cudaFuncAttributeMaxDynamicSharedMemorySize, SMEM_BYTES);

    int nbl = in_sizes[0] / (G * CH);   // 512 (b,l) groups
    int nGroups = nbl * 2;

    int dev = 0, sms = 148;
    cudaGetDevice(&dev);
    cudaDeviceGetAttribute(&sms, cudaDevAttrMultiProcessorCount, dev);
    sms &= ~1;                          // even stride -> per-CTA head parity fixed
    if (sms < 2) sms = 2;
    if (sms > nGroups) sms = nGroups;

    msa_hmma9<<<sms, NTHREADS, SMEM_BYTES>>>(x, W, b, out, nGroups, sms);
}